// round 3
// baseline (speedup 1.0000x reference)
#include <cuda_runtime.h>
#include <cuda_bf16.h>

#define BATCH_   8192
#define EMB_     1024
#define ENT_DIM_ 64
#define G_       16
#define N_REL_   5000
#define LN_EPS_  1e-5f
#define NT_      256

__global__ __launch_bounds__(NT_) void wproj_kernel(
    const float* __restrict__ ent,
    const int*   __restrict__ ids,
    const float* __restrict__ tran,
    const float* __restrict__ bias,
    const float* __restrict__ lnw,
    const float* __restrict__ lnb,
    float* __restrict__ out)
{
    __shared__ float e_sm[EMB_];
    __shared__ float red[16];

    const int row = blockIdx.x;
    const int tid = threadIdx.x;
    int r = ids[row];
    // defensive clamp: never fault even if id dtype/layout assumption is off
    r = (r < 0) ? 0 : (r >= N_REL_ ? N_REL_ - 1 : r);

    // Stage this row's entity embedding in SMEM (256 threads x float4 = 1024 f32)
    {
        float4 ev = reinterpret_cast<const float4*>(ent + (size_t)row * EMB_)[tid];
        reinterpret_cast<float4*>(e_sm)[tid] = ev;
    }
    __syncthreads();

    const float* tbase = tran + (size_t)r * (ENT_DIM_ * G_ * G_);
    const float* bbase = bias + (size_t)r * EMB_;

    float x[4];
    float s = 0.f, s2 = 0.f;

    #pragma unroll
    for (int k = 0; k < 4; k++) {
        const int o = tid + k * NT_;      // output index within row, 0..1023
        const int d = o >> 4;             // ent_dim block
        const float4* tp = reinterpret_cast<const float4*>(tbase + (size_t)o * G_);
        float4 t0 = tp[0];
        float4 t1 = tp[1];
        float4 t2 = tp[2];
        float4 t3 = tp[3];
        const float* e = e_sm + d * G_;
        float acc;
        acc  = t0.x * e[0]  + t0.y * e[1]  + t0.z * e[2]  + t0.w * e[3];
        acc += t1.x * e[4]  + t1.y * e[5]  + t1.z * e[6]  + t1.w * e[7];
        acc += t2.x * e[8]  + t2.y * e[9]  + t2.z * e[10] + t2.w * e[11];
        acc += t3.x * e[12] + t3.y * e[13] + t3.z * e[14] + t3.w * e[15];
        acc += bbase[o];
        x[k] = acc;
        s  += acc;
        s2 += acc * acc;
    }

    // Block reduction of sum and sumsq over 1024 values
    #pragma unroll
    for (int off = 16; off > 0; off >>= 1) {
        s  += __shfl_xor_sync(0xffffffffu, s,  off);
        s2 += __shfl_xor_sync(0xffffffffu, s2, off);
    }
    const int wid  = tid >> 5;
    const int lane = tid & 31;
    if (lane == 0) { red[wid] = s; red[8 + wid] = s2; }
    __syncthreads();
    if (wid == 0) {
        float a  = (lane < 8) ? red[lane]     : 0.f;
        float a2 = (lane < 8) ? red[8 + lane] : 0.f;
        #pragma unroll
        for (int off = 4; off > 0; off >>= 1) {
            a  += __shfl_xor_sync(0xffffffffu, a,  off);
            a2 += __shfl_xor_sync(0xffffffffu, a2, off);
        }
        if (lane == 0) { red[0] = a; red[1] = a2; }
    }
    __syncthreads();

    const float inv_n = 1.f / (float)EMB_;
    const float mu  = red[0] * inv_n;
    const float var = red[1] * inv_n - mu * mu;
    const float rstd = rsqrtf(var + LN_EPS_);

    float* orow = out + (size_t)row * EMB_;
    #pragma unroll
    for (int k = 0; k < 4; k++) {
        const int o = tid + k * NT_;
        orow[o] = (x[k] - mu) * rstd * __ldg(lnw + o) + __ldg(lnb + o);
    }
}

extern "C" void kernel_launch(void* const* d_in, const int* in_sizes, int n_in,
                              void* d_out, int out_size) {
    const float* ent  = (const float*)d_in[0];
    const int*   ids  = (const int*)d_in[1];
    const float* tran = (const float*)d_in[2];
    const float* bias = (const float*)d_in[3];
    const float* lnw  = (const float*)d_in[4];
    const float* lnb  = (const float*)d_in[5];
    float* out = (float*)d_out;

    wproj_kernel<<<BATCH_, NT_>>>(ent, ids, tran, bias, lnw, lnb, out);
}